// round 15
// baseline (speedup 1.0000x reference)
#include <cuda_runtime.h>
#include <cuda_fp16.h>
#include <cstdint>
#include <cstddef>

#define NMAX 100000
#define EMAX 1600000
#define GMAX 64
#define NB_MAX 128

// -------- device scratch --------
__device__ __half2 g_t1[(size_t)NMAX * 32];  // u1: N x 64 fp16 (dinv-scaled)
__device__ __half2 g_t2[(size_t)NMAX * 16];  // u2: N x 32 fp16
__device__ __half2 g_t3[(size_t)NMAX * 8];   // u3: N x 16 fp16
__device__ __half2 g_xh[(size_t)NMAX * 2];   // ux = dinv*x, padded half4
__device__ float   g_a[(size_t)NMAX * 4];    // aggregated x (N x 4) fp32
__device__ int2    g_epack[EMAX + 1];        // packed {src,dst} (+1 pad for int4 reads)
__device__ int     g_esrc[EMAX];             // src grouped by dst (CSR payload)
__device__ int     g_rowstart[NMAX + 1];
__device__ int     g_cursor[NMAX];
__device__ int     g_hist[NMAX];
__device__ float   g_dinv[NMAX];

struct Misc {
    unsigned long long state[NB_MAX];
    float pool[GMAX * 16];
    float cnt[GMAX];
    unsigned int done;
};
__device__ Misc g_m;

__device__ __forceinline__ int load_idx(const void* p, int i, int is64) {
    if (is64) return (int)__ldg((const long long*)p + i);
    return __ldg((const int*)p + i);
}

__device__ __forceinline__ int detect_is64(const void* ei, int* s_flag) {
    if (threadIdx.x < 32) {
        const int* p = (const int*)ei;
        int v = p[2 * threadIdx.x + 1];
        unsigned any = __ballot_sync(0xffffffffu, v != 0);
        if (threadIdx.x == 0) *s_flag = (any == 0) ? 1 : 0;
    }
    __syncthreads();
    return *s_flag;
}

// packed f32x2 helpers
__device__ __forceinline__ unsigned long long f2fma(unsigned long long a, unsigned long long b,
                                                    unsigned long long c) {
    unsigned long long d;
    asm("fma.rn.f32x2 %0, %1, %2, %3;" : "=l"(d) : "l"(a), "l"(b), "l"(c));
    return d;
}
__device__ __forceinline__ unsigned long long f2pack(float x, float y) {
    unsigned long long r;
    asm("mov.b64 %0, {%1, %2};" : "=l"(r) : "f"(x), "f"(y));
    return r;
}
__device__ __forceinline__ float2 f2unpack(unsigned long long v) {
    float lo, hi;
    asm("mov.b64 {%0, %1}, %2;" : "=f"(lo), "=f"(hi) : "l"(v));
    return make_float2(lo, hi);
}

// mma helpers
__device__ __forceinline__ uint32_t smem_u32(const void* p) {
    uint32_t a;
    asm("{ .reg .u64 t; cvta.to.shared.u64 t, %1; cvt.u32.u64 %0, t; }" : "=r"(a) : "l"(p));
    return a;
}
__device__ __forceinline__ void ldsm_a(uint32_t addr, uint32_t r[4]) {
    asm volatile("ldmatrix.sync.aligned.m8n8.x4.shared.b16 {%0,%1,%2,%3}, [%4];"
                 : "=r"(r[0]), "=r"(r[1]), "=r"(r[2]), "=r"(r[3]) : "r"(addr));
}
__device__ __forceinline__ void ldsm_bt(uint32_t addr, uint32_t r[2]) {
    asm volatile("ldmatrix.sync.aligned.m8n8.x2.trans.shared.b16 {%0,%1}, [%2];"
                 : "=r"(r[0]), "=r"(r[1]) : "r"(addr));
}
__device__ __forceinline__ void mma16816(float d[4], const uint32_t a[4], const uint32_t b[2]) {
    asm volatile("mma.sync.aligned.m16n8k16.row.col.f32.f16.f16.f32 "
                 "{%0,%1,%2,%3}, {%4,%5,%6,%7}, {%8,%9}, {%0,%1,%2,%3};"
                 : "+f"(d[0]), "+f"(d[1]), "+f"(d[2]), "+f"(d[3])
                 : "r"(a[0]), "r"(a[1]), "r"(a[2]), "r"(a[3]), "r"(b[0]), "r"(b[1]));
}

__device__ __forceinline__ void cvt_u2(uint2 u, float4& f) {
    float2 lo = __half22float2(*(__half2*)&u.x);
    float2 hi = __half22float2(*(__half2*)&u.y);
    f = make_float4(lo.x, lo.y, hi.x, hi.y);
}

// group gather: SUM over edges of 8B row slices (uint2 per lane), 8/4/1 batching
__device__ __forceinline__ float4 gather_rows(const uint2* __restrict__ rb, int rstride,
                                              int fl, int s0, int s1) {
    float4 A = make_float4(0.f, 0.f, 0.f, 0.f);
    float4 B = make_float4(0.f, 0.f, 0.f, 0.f);
    int e = s0;
    for (; e + 7 < s1; e += 8) {
        int i0 = g_esrc[e],     i1 = g_esrc[e + 1], i2 = g_esrc[e + 2], i3 = g_esrc[e + 3];
        int i4 = g_esrc[e + 4], i5 = g_esrc[e + 5], i6 = g_esrc[e + 6], i7 = g_esrc[e + 7];
        uint2 u0 = rb[(size_t)i0 * rstride + fl], u1 = rb[(size_t)i1 * rstride + fl];
        uint2 u2 = rb[(size_t)i2 * rstride + fl], u3 = rb[(size_t)i3 * rstride + fl];
        uint2 u4 = rb[(size_t)i4 * rstride + fl], u5 = rb[(size_t)i5 * rstride + fl];
        uint2 u6 = rb[(size_t)i6 * rstride + fl], u7 = rb[(size_t)i7 * rstride + fl];
        float4 f0, f1, f2, f3, f4, f5, f6, f7;
        cvt_u2(u0, f0); cvt_u2(u1, f1); cvt_u2(u2, f2); cvt_u2(u3, f3);
        cvt_u2(u4, f4); cvt_u2(u5, f5); cvt_u2(u6, f6); cvt_u2(u7, f7);
        A.x += f0.x + f2.x + f4.x + f6.x; A.y += f0.y + f2.y + f4.y + f6.y;
        A.z += f0.z + f2.z + f4.z + f6.z; A.w += f0.w + f2.w + f4.w + f6.w;
        B.x += f1.x + f3.x + f5.x + f7.x; B.y += f1.y + f3.y + f5.y + f7.y;
        B.z += f1.z + f3.z + f5.z + f7.z; B.w += f1.w + f3.w + f5.w + f7.w;
    }
    if (e + 3 < s1) {
        int i0 = g_esrc[e], i1 = g_esrc[e + 1], i2 = g_esrc[e + 2], i3 = g_esrc[e + 3];
        uint2 u0 = rb[(size_t)i0 * rstride + fl], u1 = rb[(size_t)i1 * rstride + fl];
        uint2 u2 = rb[(size_t)i2 * rstride + fl], u3 = rb[(size_t)i3 * rstride + fl];
        float4 f0, f1, f2, f3;
        cvt_u2(u0, f0); cvt_u2(u1, f1); cvt_u2(u2, f2); cvt_u2(u3, f3);
        A.x += f0.x + f2.x; A.y += f0.y + f2.y; A.z += f0.z + f2.z; A.w += f0.w + f2.w;
        B.x += f1.x + f3.x; B.y += f1.y + f3.y; B.z += f1.z + f3.z; B.w += f1.w + f3.w;
        e += 4;
    }
    for (; e < s1; e++) {
        uint2 u = rb[(size_t)g_esrc[e] * rstride + fl];
        float4 f; cvt_u2(u, f);
        A.x += f.x; A.y += f.y; A.z += f.z; A.w += f.w;
    }
    A.x += B.x; A.y += B.y; A.z += B.z; A.w += B.w;
    return A;
}

// histogram + pack int64->int2, 2 edges/thread vectorized (+ block 0 zeroes g_m)
__global__ void k_hist(const void* ei, int E) {
    __shared__ int s_flag;
    int is64 = detect_is64(ei, &s_flag);
    if (blockIdx.x == 0) {
        for (int i = threadIdx.x; i < (int)(sizeof(Misc) / 4); i += blockDim.x)
            ((unsigned*)&g_m)[i] = 0u;
    }
    int t = blockIdx.x * blockDim.x + threadIdx.x;
    int e = t * 2;
    if (e >= E) return;
    bool evenE = ((E & 1) == 0);
    if (e + 1 < E && evenE) {
        int s0, d0, s1, d1;
        if (is64) {
            longlong2 sv = ((const longlong2*)ei)[t];
            longlong2 dv = ((const longlong2*)ei)[(E >> 1) + t];
            s0 = (int)sv.x; s1 = (int)sv.y; d0 = (int)dv.x; d1 = (int)dv.y;
        } else {
            int2 sv = ((const int2*)ei)[t];
            int2 dv = ((const int2*)ei)[(E >> 1) + t];
            s0 = sv.x; s1 = sv.y; d0 = dv.x; d1 = dv.y;
        }
        int4 pk; pk.x = s0; pk.y = d0; pk.z = s1; pk.w = d1;
        ((int4*)g_epack)[t] = pk;
        atomicAdd(&g_hist[d0], 1);
        atomicAdd(&g_hist[d1], 1);
    } else {
        for (int q = 0; q < 2 && e + q < E; q++) {
            int s = load_idx(ei, e + q, is64);
            int d = load_idx(ei, E + e + q, is64);
            g_epack[e + q] = make_int2(s, d);
            atomicAdd(&g_hist[d], 1);
        }
    }
}

// single-pass decoupled-lookback scan + dinv + x->fp16 conversion + cursor init
__global__ void __launch_bounds__(256) k_scan(const float* __restrict__ x, int n) {
    __shared__ int sh[256];
    __shared__ int s_pref;
    int t = threadIdx.x, b = blockIdx.x;
    int base = b * 1024 + t * 4;
    int h[4]; int s = 0;
#pragma unroll
    for (int q = 0; q < 4; q++) { int i = base + q; h[q] = (i < n) ? g_hist[i] : 0; s += h[q]; }
    sh[t] = s;
    __syncthreads();
    for (int off = 1; off < 256; off <<= 1) {
        int u = (t >= off) ? sh[t - off] : 0;
        __syncthreads();
        sh[t] += u;
        __syncthreads();
    }
    int total = sh[255];
    if (t == 0) {
        unsigned long long val = ((b == 0) ? (2ULL << 32) : (1ULL << 32)) | (unsigned)total;
        atomicExch(&g_m.state[b], val);
        int pfx = 0;
        for (int j = b - 1; j >= 0;) {
            unsigned long long v;
            do { v = atomicAdd(&g_m.state[j], 0ULL); } while (v == 0ULL);
            pfx += (int)(v & 0xffffffffu);
            if ((v >> 32) == 2ULL) break;
            j--;
        }
        s_pref = pfx;
        if (b > 0) atomicExch(&g_m.state[b], (2ULL << 32) | (unsigned)(pfx + total));
    }
    __syncthreads();
    int pref = s_pref;
    int off0 = pref + sh[t] - s;
#pragma unroll
    for (int q = 0; q < 4; q++) {
        int i = base + q;
        if (i < n) {
            g_rowstart[i] = off0;
            g_cursor[i]   = off0;
            float dv = rsqrtf((float)(h[q] + 1));
            g_dinv[i] = dv;
            float x0 = x[3 * (size_t)i], x1 = x[3 * (size_t)i + 1], x2 = x[3 * (size_t)i + 2];
            g_xh[2 * (size_t)i]     = __floats2half2_rn(dv * x0, dv * x1);
            g_xh[2 * (size_t)i + 1] = __floats2half2_rn(dv * x2, 0.f);
            off0 += h[q];
        }
    }
    if (b == gridDim.x - 1 && t == 255) g_rowstart[n] = pref + total;
}

// scatter, 2 edges/thread via int4 epack reads
__global__ void k_scatter(int E) {
    int t = blockIdx.x * blockDim.x + threadIdx.x;
    int e = t * 2;
    if (e >= E) return;
    int4 p = ((const int4*)g_epack)[t];
    int pos0 = atomicAdd(&g_cursor[p.y], 1);
    g_esrc[pos0] = p.x;
    if (e + 1 < E) {
        int pos1 = atomicAdd(&g_cursor[p.w], 1);
        g_esrc[pos1] = p.z;
    }
}

// aggregate ux at dim 3 -> g_a (2 threads per node, alternate edges, shfl combine)
__global__ void k_agg0(int n) {
    int gid = blockIdx.x * blockDim.x + threadIdx.x;
    int v = gid >> 1, h = gid & 1;
    if (v >= n) return;
    int s0 = g_rowstart[v], s1 = g_rowstart[v + 1];
    const uint2* xp = (const uint2*)g_xh;
    float a0 = 0.f, a1 = 0.f, a2 = 0.f, b0 = 0.f, b1 = 0.f, b2 = 0.f;
    int e = s0 + h;
    for (; e + 6 < s1; e += 8) {
        uint2 ra = xp[g_esrc[e]],     rb = xp[g_esrc[e + 2]];
        uint2 rc = xp[g_esrc[e + 4]], rd = xp[g_esrc[e + 6]];
        float2 fa = __half22float2(*(__half2*)&ra.x); float fa2 = __low2float(*(__half2*)&ra.y);
        float2 fb = __half22float2(*(__half2*)&rb.x); float fb2 = __low2float(*(__half2*)&rb.y);
        float2 fc = __half22float2(*(__half2*)&rc.x); float fc2 = __low2float(*(__half2*)&rc.y);
        float2 fd = __half22float2(*(__half2*)&rd.x); float fd2 = __low2float(*(__half2*)&rd.y);
        a0 += fa.x + fc.x; a1 += fa.y + fc.y; a2 += fa2 + fc2;
        b0 += fb.x + fd.x; b1 += fb.y + fd.y; b2 += fb2 + fd2;
    }
    for (; e < s1; e += 2) {
        uint2 ra = xp[g_esrc[e]];
        float2 fa = __half22float2(*(__half2*)&ra.x); float fa2 = __low2float(*(__half2*)&ra.y);
        a0 += fa.x; a1 += fa.y; a2 += fa2;
    }
    float r0 = a0 + b0, r1 = a1 + b1, r2 = a2 + b2;
    r0 += __shfl_xor_sync(0xffffffffu, r0, 1);
    r1 += __shfl_xor_sync(0xffffffffu, r1, 1);
    r2 += __shfl_xor_sync(0xffffffffu, r2, 1);
    if (h == 0) {
        uint2 rs = xp[v];
        float2 fs = __half22float2(*(__half2*)&rs.x); float fs2 = __low2float(*(__half2*)&rs.y);
        float dv = g_dinv[v];
        *(float4*)(g_a + 4 * (size_t)v) =
            make_float4(dv * (r0 + fs.x), dv * (r1 + fs.y), dv * (r2 + fs2), 0.f);
    }
}

// layers 0+1 on tensor cores, 4 node-tiles (512 nodes) per block
#define HS_STR 136
#define W1_STR 72
__global__ void __launch_bounds__(256)
k_l01(const float* __restrict__ W0, const float* __restrict__ b0,
      const float* __restrict__ W1, int n) {
    extern __shared__ char sm_[];
    float4* W0c = (float4*)sm_;                       // 2048 B
    __half* W1h = (__half*)(sm_ + 2048);              // 18432 B
    __half* Hs  = (__half*)(sm_ + 2048 + 18432);      // 34816 B
    int tid = threadIdx.x;
    if (tid < 128) W0c[tid] = make_float4(W0[tid], W0[128 + tid], W0[256 + tid], b0[tid]);
    for (int i = tid; i < 128 * 64; i += 256) {
        int k = i >> 6, nn = i & 63;
        W1h[k * W1_STR + nn] = __float2half_rn(W1[i]);
    }
    __syncthreads();

    int w = tid >> 5, lane = tid & 31;
    int m0 = (w & 7) * 16;
    int gid = lane >> 2, qid = lane & 3;
    int a_row = m0 + ((lane >> 3) & 1) * 8 + (lane & 7);
    int a_col0 = ((lane >> 4) & 1) * 8;
    int b_lane = lane & 15;
    uint32_t hsb = smem_u32(Hs);
    uint32_t w1b = smem_u32(W1h);

#pragma unroll
    for (int tile = 0; tile < 4; tile++) {
        int base = (blockIdx.x * 4 + tile) * 128;
        if (base >= n) break;

        // Phase A: h = relu(a·W0 + b0) -> Hs fp16 (2 threads per node)
        {
            int node = tid >> 1, jh = tid & 1;
            int v = base + node;
            float4 a = (v < n) ? *(const float4*)(g_a + 4 * (size_t)v) : make_float4(0, 0, 0, 0);
            __half2* hrow = (__half2*)(Hs + node * HS_STR + jh * 64);
#pragma unroll
            for (int k2 = 0; k2 < 32; k2++) {
                float4 w0 = W0c[jh * 64 + 2 * k2];
                float4 w1 = W0c[jh * 64 + 2 * k2 + 1];
                float h0 = fmaxf(fmaf(a.x, w0.x, fmaf(a.y, w0.y, fmaf(a.z, w0.z, w0.w))), 0.f);
                float h1 = fmaxf(fmaf(a.x, w1.x, fmaf(a.y, w1.y, fmaf(a.z, w1.z, w1.w))), 0.f);
                hrow[k2] = __floats2half2_rn(h0, h1);
            }
        }
        __syncthreads();

        // Phase B: 128x128 @ 128x64 HMMA
        float acc[8][4];
#pragma unroll
        for (int nt = 0; nt < 8; nt++)
#pragma unroll
            for (int c = 0; c < 4; c++) acc[nt][c] = 0.f;

#pragma unroll
        for (int ks = 0; ks < 8; ks++) {
            uint32_t af[4];
            ldsm_a(hsb + (uint32_t)(a_row * HS_STR + ks * 16 + a_col0) * 2, af);
            int b_row = ks * 16 + b_lane;
#pragma unroll
            for (int nt = 0; nt < 8; nt++) {
                uint32_t bf[2];
                ldsm_bt(w1b + (uint32_t)(b_row * W1_STR + nt * 8) * 2, bf);
                mma16816(acc[nt], af, bf);
            }
        }

        int r0 = base + m0 + gid, r1 = r0 + 8;
        float s0 = (r0 < n) ? 2.f * g_dinv[r0] : 0.f;
        float s1 = (r1 < n) ? 2.f * g_dinv[r1] : 0.f;
        __half* t1h = (__half*)g_t1;
#pragma unroll
        for (int nt = 0; nt < 8; nt++) {
            int col = nt * 8 + qid * 2;
            if (r0 < n)
                *(__half2*)(t1h + (size_t)r0 * 64 + col) = __floats2half2_rn(s0 * acc[nt][0], s0 * acc[nt][1]);
            if (r1 < n)
                *(__half2*)(t1h + (size_t)r1 * 64 + col) = __floats2half2_rn(s1 * acc[nt][2], s1 * acc[nt][3]);
        }
        __syncthreads();   // Hs reuse across tiles
    }
}

// fused agg(64) + GEMM(64->32): half-warp per node (16 lanes x uint2 = 128B row)
__global__ void __launch_bounds__(256)
k_f1(const float* __restrict__ bias, const float* __restrict__ Wg, int n) {
    constexpr int STR = 65;
    __shared__ float Hs[64 * STR];
    __shared__ float Ws[64 * 32];
    __shared__ float bs[64];
    int tid = threadIdx.x;
    for (int i = tid; i < 64 * 32; i += 256) Ws[i] = Wg[i];
    if (tid < 64) bs[tid] = bias[tid];
    int hw = tid >> 4, fl = tid & 15;
    int base = blockIdx.x * 64;
    const uint2* rb = (const uint2*)g_t1;

#pragma unroll
    for (int i = 0; i < 4; i++) {
        int nd = hw * 4 + i;
        int v = base + nd;
        if (v < n) {
            int s0 = g_rowstart[v], s1 = g_rowstart[v + 1];
            float4 A = gather_rows(rb, 16, fl, s0, s1);
            uint2 us = rb[(size_t)v * 16 + fl];
            float4 fs; cvt_u2(us, fs);
            float dv = g_dinv[v];
            float* hr = &Hs[nd * STR + 4 * fl];
            hr[0] = fmaxf(dv * (A.x + fs.x) + bs[4 * fl + 0], 0.f);
            hr[1] = fmaxf(dv * (A.y + fs.y) + bs[4 * fl + 1], 0.f);
            hr[2] = fmaxf(dv * (A.z + fs.z) + bs[4 * fl + 2], 0.f);
            hr[3] = fmaxf(dv * (A.w + fs.w) + bs[4 * fl + 3], 0.f);
        }
    }
    __syncthreads();

    int nd = tid & 63, jh = tid >> 6;
    int j0 = jh * 8;
    unsigned long long acc2[4] = {0ull, 0ull, 0ull, 0ull};
    for (int k = 0; k < 64; k++) {
        float hv = Hs[nd * STR + k];
        unsigned long long h2 = f2pack(hv, hv);
        ulonglong2 wA = *(const ulonglong2*)&Ws[k * 32 + j0];
        ulonglong2 wB = *(const ulonglong2*)&Ws[k * 32 + j0 + 4];
        acc2[0] = f2fma(h2, wA.x, acc2[0]);
        acc2[1] = f2fma(h2, wA.y, acc2[1]);
        acc2[2] = f2fma(h2, wB.x, acc2[2]);
        acc2[3] = f2fma(h2, wB.y, acc2[3]);
    }
    int v = base + nd;
    if (v < n) {
        float s = 2.f * g_dinv[v];
        uint4 pk;
#pragma unroll
        for (int c = 0; c < 4; c++) {
            float2 f = f2unpack(acc2[c]);
            __half2 hh = __floats2half2_rn(s * f.x, s * f.y);
            ((uint32_t*)&pk)[c] = *(uint32_t*)&hh;
        }
        *(uint4*)(g_t2 + (size_t)v * 16 + jh * 4) = pk;
    }
}

// fused agg(32) + GEMM(32->16): 8-lane group per node (8 x uint2 = 64B row)
__global__ void __launch_bounds__(256)
k_f2(const float* __restrict__ bias, const float* __restrict__ Wg, int n) {
    constexpr int STR = 33;
    __shared__ float Hs[64 * STR];
    __shared__ float Ws[32 * 16];
    __shared__ float bs[32];
    int tid = threadIdx.x;
    for (int i = tid; i < 32 * 16; i += 256) Ws[i] = Wg[i];
    if (tid < 32) bs[tid] = bias[tid];
    int qw = tid >> 3, fl = tid & 7;
    int base = blockIdx.x * 64;
    const uint2* rb = (const uint2*)g_t2;

#pragma unroll
    for (int i = 0; i < 2; i++) {
        int nd = qw * 2 + i;
        int v = base + nd;
        if (v < n) {
            int s0 = g_rowstart[v], s1 = g_rowstart[v + 1];
            float4 A = gather_rows(rb, 8, fl, s0, s1);
            uint2 us = rb[(size_t)v * 8 + fl];
            float4 fs; cvt_u2(us, fs);
            float dv = g_dinv[v];
            float* hr = &Hs[nd * STR + 4 * fl];
            hr[0] = fmaxf(dv * (A.x + fs.x) + bs[4 * fl + 0], 0.f);
            hr[1] = fmaxf(dv * (A.y + fs.y) + bs[4 * fl + 1], 0.f);
            hr[2] = fmaxf(dv * (A.z + fs.z) + bs[4 * fl + 2], 0.f);
            hr[3] = fmaxf(dv * (A.w + fs.w) + bs[4 * fl + 3], 0.f);
        }
    }
    __syncthreads();

    int nd = tid & 63, jh = tid >> 6;
    int j0 = jh * 4;
    unsigned long long acc2[2] = {0ull, 0ull};
    for (int k = 0; k < 32; k++) {
        float hv = Hs[nd * STR + k];
        unsigned long long h2 = f2pack(hv, hv);
        ulonglong2 wv = *(const ulonglong2*)&Ws[k * 16 + j0];
        acc2[0] = f2fma(h2, wv.x, acc2[0]);
        acc2[1] = f2fma(h2, wv.y, acc2[1]);
    }
    int v = base + nd;
    if (v < n) {
        float s = 2.f * g_dinv[v];
        float2 f0 = f2unpack(acc2[0]), f1 = f2unpack(acc2[1]);
        uint2 pk;
        __half2 h0 = __floats2half2_rn(s * f0.x, s * f0.y);
        __half2 h1 = __floats2half2_rn(s * f1.x, s * f1.y);
        pk.x = *(uint32_t*)&h0; pk.y = *(uint32_t*)&h1;
        *(uint2*)(g_t3 + (size_t)v * 8 + jh * 2) = pk;
    }
}

// final agg (dim 16, 4-lane group per node) + block pooling + last-block MLP head
__global__ void __launch_bounds__(256)
k_aggpool(const float* __restrict__ bias, const void* batch, const void* ei,
          const float* __restrict__ fc1w, const float* __restrict__ fc1b,
          const float* __restrict__ fc2w, const float* __restrict__ fc2b,
          float* __restrict__ out, int n, int G) {
    __shared__ float spool[GMAX * 16];
    __shared__ float scnt[GMAX];
    __shared__ int sgmin, sgmax;
    __shared__ int s_flag;
    __shared__ bool s_last;
    int is64 = detect_is64(ei, &s_flag);
    int tid = threadIdx.x;
    for (int i = tid; i < GMAX * 16; i += 256) spool[i] = 0.f;
    if (tid < GMAX) scnt[tid] = 0.f;
    if (tid == 0) { sgmin = GMAX; sgmax = -1; }
    __syncthreads();
    int grp = tid >> 2, fl = tid & 3;
    int v = blockIdx.x * 64 + grp;
    const uint2* rb = (const uint2*)g_t3;
    if (v < n) {
        int s0 = g_rowstart[v], s1 = g_rowstart[v + 1];
        float4 A = gather_rows(rb, 4, fl, s0, s1);
        uint2 us = rb[(size_t)v * 4 + fl];
        float4 fs; cvt_u2(us, fs);
        float dv = g_dinv[v];
        int g = load_idx(batch, v, is64);
        int cb = 4 * fl;
        float h0 = fmaxf(dv * (A.x + fs.x) + bias[cb + 0], 0.f);
        float h1 = fmaxf(dv * (A.y + fs.y) + bias[cb + 1], 0.f);
        float h2 = fmaxf(dv * (A.z + fs.z) + bias[cb + 2], 0.f);
        float h3 = fmaxf(dv * (A.w + fs.w) + bias[cb + 3], 0.f);
        atomicAdd(&spool[g * 16 + cb + 0], h0);
        atomicAdd(&spool[g * 16 + cb + 1], h1);
        atomicAdd(&spool[g * 16 + cb + 2], h2);
        atomicAdd(&spool[g * 16 + cb + 3], h3);
        if (fl == 0) {
            atomicAdd(&scnt[g], 1.f);
            atomicMin(&sgmin, g);
            atomicMax(&sgmax, g);
        }
    }
    __syncthreads();
    int lo = sgmin, hi = sgmax;
    if (hi >= lo) {
        int rows = hi - lo + 1;
        for (int i = tid; i < rows * 16; i += 256) {
            float val = spool[(lo + i / 16) * 16 + (i & 15)];
            if (val != 0.f) atomicAdd(&g_m.pool[(lo + i / 16) * 16 + (i & 15)], val);
        }
        for (int i = tid; i < rows; i += 256) {
            float c = scnt[lo + i];
            if (c != 0.f) atomicAdd(&g_m.cnt[lo + i], c);
        }
    }
    if (tid == 0) {
        __threadfence();
        unsigned r = atomicAdd(&g_m.done, 1u);
        s_last = (r == gridDim.x - 1);
    }
    __syncthreads();
    if (s_last && tid < G) {
        int g = tid;
        float c = fmaxf(g_m.cnt[g], 1.f);
        float p[16];
#pragma unroll
        for (int j = 0; j < 16; j++) p[j] = g_m.pool[g * 16 + j] / c;
        float z[8];
#pragma unroll
        for (int i = 0; i < 8; i++) {
            float aa = fc1b[i];
#pragma unroll
            for (int j = 0; j < 16; j++) aa += p[j] * fc1w[j * 8 + i];
            z[i] = fmaxf(aa, 0.f);
        }
#pragma unroll
        for (int o = 0; o < 4; o++) {
            float aa = fc2b[o];
#pragma unroll
            for (int i = 0; i < 8; i++) aa += z[i] * fc2w[i * 4 + o];
            out[g * 4 + o] = aa;
        }
    }
}

// ------------------------------- host -------------------------------
extern "C" void kernel_launch(void* const* d_in, const int* in_sizes, int n_in,
                              void* d_out, int out_size) {
    const float* x   = (const float*)d_in[0];
    const void*  ei  = d_in[1];
    const void*  bat = d_in[2];
    const float* W0 = (const float*)d_in[3];  const float* b0 = (const float*)d_in[4];
    const float* W1 = (const float*)d_in[5];  const float* b1 = (const float*)d_in[6];
    const float* W2 = (const float*)d_in[7];  const float* b2 = (const float*)d_in[8];
    const float* W3 = (const float*)d_in[9];  const float* b3 = (const float*)d_in[10];
    const float* fc1w = (const float*)d_in[11]; const float* fc1b = (const float*)d_in[12];
    const float* fc2w = (const float*)d_in[13]; const float* fc2b = (const float*)d_in[14];
    float* out = (float*)d_out;

    int N = in_sizes[0] / 3;
    int E = in_sizes[1] / 2;
    int G = out_size / 4;
    if (N > NMAX || E > EMAX || G > GMAX) return;

    void* pHist = nullptr;
    cudaGetSymbolAddress(&pHist, g_hist);

    int gE2 = ((E + 1) / 2 + 255) / 256;   // 2 edges per thread
    int nb = (N + 1023) / 1024;
    int smemL01 = 2048 + 18432 + 34816;   // 55296 B

    static int s_attr_done = 0;
    if (!s_attr_done) {
        cudaFuncSetAttribute(k_l01, cudaFuncAttributeMaxDynamicSharedMemorySize, smemL01);
        s_attr_done = 1;
    }

    cudaMemsetAsync(pHist, 0, (size_t)N * sizeof(int));
    k_hist<<<gE2, 256>>>(ei, E);
    k_scan<<<nb, 256>>>(x, N);
    k_scatter<<<gE2, 256>>>(E);
    k_agg0<<<(2 * N + 255) / 256, 256>>>(N);
    k_l01<<<(N + 511) / 512, 256, smemL01>>>(W0, b0, W1, N);
    k_f1<<<(N + 63) / 64, 256>>>(b1, W2, N);
    k_f2<<<(N + 63) / 64, 256>>>(b2, W3, N);
    k_aggpool<<<(N + 63) / 64, 256>>>(b3, bat, ei, fc1w, fc1b, fc2w, fc2b, out, N, G);
}

// round 16
// speedup vs baseline: 1.0355x; 1.0355x over previous
#include <cuda_runtime.h>
#include <cuda_fp16.h>
#include <cstdint>
#include <cstddef>

#define NMAX 100000
#define EMAX 1600000
#define GMAX 64
#define NB_MAX 128

// -------- device scratch --------
__device__ __half2 g_t1[(size_t)NMAX * 32];  // u1: N x 64 fp16 (dinv-scaled)
__device__ __half2 g_t2[(size_t)NMAX * 16];  // u2: N x 32 fp16
__device__ __half2 g_t3[(size_t)NMAX * 8];   // u3: N x 16 fp16
__device__ __half2 g_xh[(size_t)NMAX * 2];   // ux = dinv*x, padded half4
__device__ float   g_a[(size_t)NMAX * 4];    // aggregated x (N x 4) fp32
__device__ int2    g_epack[EMAX];            // packed {src,dst} int32
__device__ int     g_esrc[EMAX];             // src grouped by dst (CSR payload)
__device__ int     g_rowstart[NMAX + 1];
__device__ int     g_cursor[NMAX];
__device__ int     g_hist[NMAX];
__device__ float   g_dinv[NMAX];

struct Misc {
    unsigned long long state[NB_MAX];
    float pool[GMAX * 16];
    float cnt[GMAX];
    unsigned int done;
};
__device__ Misc g_m;

__device__ __forceinline__ int load_idx(const void* p, int i, int is64) {
    if (is64) return (int)__ldg((const long long*)p + i);
    return __ldg((const int*)p + i);
}

__device__ __forceinline__ int detect_is64(const void* ei, int* s_flag) {
    if (threadIdx.x < 32) {
        const int* p = (const int*)ei;
        int v = p[2 * threadIdx.x + 1];
        unsigned any = __ballot_sync(0xffffffffu, v != 0);
        if (threadIdx.x == 0) *s_flag = (any == 0) ? 1 : 0;
    }
    __syncthreads();
    return *s_flag;
}

// packed f32x2 helpers
__device__ __forceinline__ unsigned long long f2fma(unsigned long long a, unsigned long long b,
                                                    unsigned long long c) {
    unsigned long long d;
    asm("fma.rn.f32x2 %0, %1, %2, %3;" : "=l"(d) : "l"(a), "l"(b), "l"(c));
    return d;
}
__device__ __forceinline__ unsigned long long f2pack(float x, float y) {
    unsigned long long r;
    asm("mov.b64 %0, {%1, %2};" : "=l"(r) : "f"(x), "f"(y));
    return r;
}
__device__ __forceinline__ float2 f2unpack(unsigned long long v) {
    float lo, hi;
    asm("mov.b64 {%0, %1}, %2;" : "=f"(lo), "=f"(hi) : "l"(v));
    return make_float2(lo, hi);
}

// mma helpers
__device__ __forceinline__ uint32_t smem_u32(const void* p) {
    uint32_t a;
    asm("{ .reg .u64 t; cvta.to.shared.u64 t, %1; cvt.u32.u64 %0, t; }" : "=r"(a) : "l"(p));
    return a;
}
__device__ __forceinline__ void ldsm_a(uint32_t addr, uint32_t r[4]) {
    asm volatile("ldmatrix.sync.aligned.m8n8.x4.shared.b16 {%0,%1,%2,%3}, [%4];"
                 : "=r"(r[0]), "=r"(r[1]), "=r"(r[2]), "=r"(r[3]) : "r"(addr));
}
__device__ __forceinline__ void ldsm_bt(uint32_t addr, uint32_t r[2]) {
    asm volatile("ldmatrix.sync.aligned.m8n8.x2.trans.shared.b16 {%0,%1}, [%2];"
                 : "=r"(r[0]), "=r"(r[1]) : "r"(addr));
}
__device__ __forceinline__ void mma16816(float d[4], const uint32_t a[4], const uint32_t b[2]) {
    asm volatile("mma.sync.aligned.m16n8k16.row.col.f32.f16.f16.f32 "
                 "{%0,%1,%2,%3}, {%4,%5,%6,%7}, {%8,%9}, {%0,%1,%2,%3};"
                 : "+f"(d[0]), "+f"(d[1]), "+f"(d[2]), "+f"(d[3])
                 : "r"(a[0]), "r"(a[1]), "r"(a[2]), "r"(a[3]), "r"(b[0]), "r"(b[1]));
}

__device__ __forceinline__ void cvt_u2(uint2 u, float4& f) {
    float2 lo = __half22float2(*(__half2*)&u.x);
    float2 hi = __half22float2(*(__half2*)&u.y);
    f = make_float4(lo.x, lo.y, hi.x, hi.y);
}

// group gather: SUM over edges of 8B row slices (uint2 per lane), 8/4/1 batching
__device__ __forceinline__ float4 gather_rows(const uint2* __restrict__ rb, int rstride,
                                              int fl, int s0, int s1) {
    float4 A = make_float4(0.f, 0.f, 0.f, 0.f);
    float4 B = make_float4(0.f, 0.f, 0.f, 0.f);
    int e = s0;
    for (; e + 7 < s1; e += 8) {
        int i0 = g_esrc[e],     i1 = g_esrc[e + 1], i2 = g_esrc[e + 2], i3 = g_esrc[e + 3];
        int i4 = g_esrc[e + 4], i5 = g_esrc[e + 5], i6 = g_esrc[e + 6], i7 = g_esrc[e + 7];
        uint2 u0 = rb[(size_t)i0 * rstride + fl], u1 = rb[(size_t)i1 * rstride + fl];
        uint2 u2 = rb[(size_t)i2 * rstride + fl], u3 = rb[(size_t)i3 * rstride + fl];
        uint2 u4 = rb[(size_t)i4 * rstride + fl], u5 = rb[(size_t)i5 * rstride + fl];
        uint2 u6 = rb[(size_t)i6 * rstride + fl], u7 = rb[(size_t)i7 * rstride + fl];
        float4 f0, f1, f2, f3, f4, f5, f6, f7;
        cvt_u2(u0, f0); cvt_u2(u1, f1); cvt_u2(u2, f2); cvt_u2(u3, f3);
        cvt_u2(u4, f4); cvt_u2(u5, f5); cvt_u2(u6, f6); cvt_u2(u7, f7);
        A.x += f0.x + f2.x + f4.x + f6.x; A.y += f0.y + f2.y + f4.y + f6.y;
        A.z += f0.z + f2.z + f4.z + f6.z; A.w += f0.w + f2.w + f4.w + f6.w;
        B.x += f1.x + f3.x + f5.x + f7.x; B.y += f1.y + f3.y + f5.y + f7.y;
        B.z += f1.z + f3.z + f5.z + f7.z; B.w += f1.w + f3.w + f5.w + f7.w;
    }
    if (e + 3 < s1) {
        int i0 = g_esrc[e], i1 = g_esrc[e + 1], i2 = g_esrc[e + 2], i3 = g_esrc[e + 3];
        uint2 u0 = rb[(size_t)i0 * rstride + fl], u1 = rb[(size_t)i1 * rstride + fl];
        uint2 u2 = rb[(size_t)i2 * rstride + fl], u3 = rb[(size_t)i3 * rstride + fl];
        float4 f0, f1, f2, f3;
        cvt_u2(u0, f0); cvt_u2(u1, f1); cvt_u2(u2, f2); cvt_u2(u3, f3);
        A.x += f0.x + f2.x; A.y += f0.y + f2.y; A.z += f0.z + f2.z; A.w += f0.w + f2.w;
        B.x += f1.x + f3.x; B.y += f1.y + f3.y; B.z += f1.z + f3.z; B.w += f1.w + f3.w;
        e += 4;
    }
    for (; e < s1; e++) {
        uint2 u = rb[(size_t)g_esrc[e] * rstride + fl];
        float4 f; cvt_u2(u, f);
        A.x += f.x; A.y += f.y; A.z += f.z; A.w += f.w;
    }
    A.x += B.x; A.y += B.y; A.z += B.z; A.w += B.w;
    return A;
}

// histogram + pack int64->int2 (+ block 0 zeroes g_m)
__global__ void k_hist(const void* ei, int E) {
    __shared__ int s_flag;
    int is64 = detect_is64(ei, &s_flag);
    if (blockIdx.x == 0) {
        for (int i = threadIdx.x; i < (int)(sizeof(Misc) / 4); i += blockDim.x)
            ((unsigned*)&g_m)[i] = 0u;
    }
    int e = blockIdx.x * blockDim.x + threadIdx.x;
    if (e >= E) return;
    int s = load_idx(ei, e, is64);
    int d = load_idx(ei, E + e, is64);
    g_epack[e] = make_int2(s, d);
    atomicAdd(&g_hist[d], 1);
}

// single-pass decoupled-lookback scan + dinv + x->fp16 conversion + cursor init
__global__ void __launch_bounds__(256) k_scan(const float* __restrict__ x, int n) {
    __shared__ int sh[256];
    __shared__ int s_pref;
    int t = threadIdx.x, b = blockIdx.x;
    int base = b * 1024 + t * 4;
    int h[4]; int s = 0;
#pragma unroll
    for (int q = 0; q < 4; q++) { int i = base + q; h[q] = (i < n) ? g_hist[i] : 0; s += h[q]; }
    sh[t] = s;
    __syncthreads();
    for (int off = 1; off < 256; off <<= 1) {
        int u = (t >= off) ? sh[t - off] : 0;
        __syncthreads();
        sh[t] += u;
        __syncthreads();
    }
    int total = sh[255];
    if (t == 0) {
        unsigned long long val = ((b == 0) ? (2ULL << 32) : (1ULL << 32)) | (unsigned)total;
        atomicExch(&g_m.state[b], val);
        int pfx = 0;
        for (int j = b - 1; j >= 0;) {
            unsigned long long v;
            do { v = atomicAdd(&g_m.state[j], 0ULL); } while (v == 0ULL);
            pfx += (int)(v & 0xffffffffu);
            if ((v >> 32) == 2ULL) break;
            j--;
        }
        s_pref = pfx;
        if (b > 0) atomicExch(&g_m.state[b], (2ULL << 32) | (unsigned)(pfx + total));
    }
    __syncthreads();
    int pref = s_pref;
    int off0 = pref + sh[t] - s;
#pragma unroll
    for (int q = 0; q < 4; q++) {
        int i = base + q;
        if (i < n) {
            g_rowstart[i] = off0;
            g_cursor[i]   = off0;
            float dv = rsqrtf((float)(h[q] + 1));
            g_dinv[i] = dv;
            float x0 = x[3 * (size_t)i], x1 = x[3 * (size_t)i + 1], x2 = x[3 * (size_t)i + 2];
            g_xh[2 * (size_t)i]     = __floats2half2_rn(dv * x0, dv * x1);
            g_xh[2 * (size_t)i + 1] = __floats2half2_rn(dv * x2, 0.f);
            off0 += h[q];
        }
    }
    if (b == gridDim.x - 1 && t == 255) g_rowstart[n] = pref + total;
}

__global__ void k_scatter(int E) {
    int e = blockIdx.x * blockDim.x + threadIdx.x;
    if (e >= E) return;
    int2 sd = g_epack[e];
    int pos = atomicAdd(&g_cursor[sd.y], 1);
    g_esrc[pos] = sd.x;
}

// aggregate ux at dim 3 -> g_a (2 threads per node, alternate edges, shfl combine)
__global__ void k_agg0(int n) {
    int gid = blockIdx.x * blockDim.x + threadIdx.x;
    int v = gid >> 1, h = gid & 1;
    if (v >= n) return;
    int s0 = g_rowstart[v], s1 = g_rowstart[v + 1];
    const uint2* xp = (const uint2*)g_xh;
    float a0 = 0.f, a1 = 0.f, a2 = 0.f, b0 = 0.f, b1 = 0.f, b2 = 0.f;
    int e = s0 + h;
    for (; e + 6 < s1; e += 8) {
        uint2 ra = xp[g_esrc[e]],     rb = xp[g_esrc[e + 2]];
        uint2 rc = xp[g_esrc[e + 4]], rd = xp[g_esrc[e + 6]];
        float2 fa = __half22float2(*(__half2*)&ra.x); float fa2 = __low2float(*(__half2*)&ra.y);
        float2 fb = __half22float2(*(__half2*)&rb.x); float fb2 = __low2float(*(__half2*)&rb.y);
        float2 fc = __half22float2(*(__half2*)&rc.x); float fc2 = __low2float(*(__half2*)&rc.y);
        float2 fd = __half22float2(*(__half2*)&rd.x); float fd2 = __low2float(*(__half2*)&rd.y);
        a0 += fa.x + fc.x; a1 += fa.y + fc.y; a2 += fa2 + fc2;
        b0 += fb.x + fd.x; b1 += fb.y + fd.y; b2 += fb2 + fd2;
    }
    for (; e < s1; e += 2) {
        uint2 ra = xp[g_esrc[e]];
        float2 fa = __half22float2(*(__half2*)&ra.x); float fa2 = __low2float(*(__half2*)&ra.y);
        a0 += fa.x; a1 += fa.y; a2 += fa2;
    }
    float r0 = a0 + b0, r1 = a1 + b1, r2 = a2 + b2;
    r0 += __shfl_xor_sync(0xffffffffu, r0, 1);
    r1 += __shfl_xor_sync(0xffffffffu, r1, 1);
    r2 += __shfl_xor_sync(0xffffffffu, r2, 1);
    if (h == 0) {
        uint2 rs = xp[v];
        float2 fs = __half22float2(*(__half2*)&rs.x); float fs2 = __low2float(*(__half2*)&rs.y);
        float dv = g_dinv[v];
        *(float4*)(g_a + 4 * (size_t)v) =
            make_float4(dv * (r0 + fs.x), dv * (r1 + fs.y), dv * (r2 + fs2), 0.f);
    }
}

// layers 0+1 on tensor cores, 3 node-tiles (384 nodes) per block
#define HS_STR 136
#define W1_STR 72
__global__ void __launch_bounds__(256)
k_l01(const float* __restrict__ W0, const float* __restrict__ b0,
      const float* __restrict__ W1, int n) {
    extern __shared__ char sm_[];
    float4* W0c = (float4*)sm_;                       // 2048 B
    __half* W1h = (__half*)(sm_ + 2048);              // 18432 B
    __half* Hs  = (__half*)(sm_ + 2048 + 18432);      // 34816 B
    int tid = threadIdx.x;
    if (tid < 128) W0c[tid] = make_float4(W0[tid], W0[128 + tid], W0[256 + tid], b0[tid]);
    for (int i = tid; i < 128 * 64; i += 256) {
        int k = i >> 6, nn = i & 63;
        W1h[k * W1_STR + nn] = __float2half_rn(W1[i]);
    }
    __syncthreads();

    int w = tid >> 5, lane = tid & 31;
    int m0 = (w & 7) * 16;
    int gid = lane >> 2, qid = lane & 3;
    int a_row = m0 + ((lane >> 3) & 1) * 8 + (lane & 7);
    int a_col0 = ((lane >> 4) & 1) * 8;
    int b_lane = lane & 15;
    uint32_t hsb = smem_u32(Hs);
    uint32_t w1b = smem_u32(W1h);

#pragma unroll
    for (int tile = 0; tile < 3; tile++) {
        int base = (blockIdx.x * 3 + tile) * 128;
        if (base >= n) break;

        // Phase A: h = relu(a·W0 + b0) -> Hs fp16 (2 threads per node)
        {
            int node = tid >> 1, jh = tid & 1;
            int v = base + node;
            float4 a = (v < n) ? *(const float4*)(g_a + 4 * (size_t)v) : make_float4(0, 0, 0, 0);
            __half2* hrow = (__half2*)(Hs + node * HS_STR + jh * 64);
#pragma unroll
            for (int k2 = 0; k2 < 32; k2++) {
                float4 w0 = W0c[jh * 64 + 2 * k2];
                float4 w1 = W0c[jh * 64 + 2 * k2 + 1];
                float h0 = fmaxf(fmaf(a.x, w0.x, fmaf(a.y, w0.y, fmaf(a.z, w0.z, w0.w))), 0.f);
                float h1 = fmaxf(fmaf(a.x, w1.x, fmaf(a.y, w1.y, fmaf(a.z, w1.z, w1.w))), 0.f);
                hrow[k2] = __floats2half2_rn(h0, h1);
            }
        }
        __syncthreads();

        // Phase B: 128x128 @ 128x64 HMMA
        float acc[8][4];
#pragma unroll
        for (int nt = 0; nt < 8; nt++)
#pragma unroll
            for (int c = 0; c < 4; c++) acc[nt][c] = 0.f;

#pragma unroll
        for (int ks = 0; ks < 8; ks++) {
            uint32_t af[4];
            ldsm_a(hsb + (uint32_t)(a_row * HS_STR + ks * 16 + a_col0) * 2, af);
            int b_row = ks * 16 + b_lane;
#pragma unroll
            for (int nt = 0; nt < 8; nt++) {
                uint32_t bf[2];
                ldsm_bt(w1b + (uint32_t)(b_row * W1_STR + nt * 8) * 2, bf);
                mma16816(acc[nt], af, bf);
            }
        }

        int r0 = base + m0 + gid, r1 = r0 + 8;
        float s0 = (r0 < n) ? 2.f * g_dinv[r0] : 0.f;
        float s1 = (r1 < n) ? 2.f * g_dinv[r1] : 0.f;
        __half* t1h = (__half*)g_t1;
#pragma unroll
        for (int nt = 0; nt < 8; nt++) {
            int col = nt * 8 + qid * 2;
            if (r0 < n)
                *(__half2*)(t1h + (size_t)r0 * 64 + col) = __floats2half2_rn(s0 * acc[nt][0], s0 * acc[nt][1]);
            if (r1 < n)
                *(__half2*)(t1h + (size_t)r1 * 64 + col) = __floats2half2_rn(s1 * acc[nt][2], s1 * acc[nt][3]);
        }
        __syncthreads();   // Hs reuse across tiles
    }
}

// fused agg(64) + GEMM(64->32): half-warp per node (16 lanes x uint2 = 128B row)
__global__ void __launch_bounds__(256)
k_f1(const float* __restrict__ bias, const float* __restrict__ Wg, int n) {
    constexpr int STR = 65;
    __shared__ float Hs[64 * STR];
    __shared__ float Ws[64 * 32];
    __shared__ float bs[64];
    int tid = threadIdx.x;
    for (int i = tid; i < 64 * 32; i += 256) Ws[i] = Wg[i];
    if (tid < 64) bs[tid] = bias[tid];
    int hw = tid >> 4, fl = tid & 15;
    int base = blockIdx.x * 64;
    const uint2* rb = (const uint2*)g_t1;

#pragma unroll
    for (int i = 0; i < 4; i++) {
        int nd = hw * 4 + i;
        int v = base + nd;
        if (v < n) {
            int s0 = g_rowstart[v], s1 = g_rowstart[v + 1];
            float4 A = gather_rows(rb, 16, fl, s0, s1);
            uint2 us = rb[(size_t)v * 16 + fl];
            float4 fs; cvt_u2(us, fs);
            float dv = g_dinv[v];
            float* hr = &Hs[nd * STR + 4 * fl];
            hr[0] = fmaxf(dv * (A.x + fs.x) + bs[4 * fl + 0], 0.f);
            hr[1] = fmaxf(dv * (A.y + fs.y) + bs[4 * fl + 1], 0.f);
            hr[2] = fmaxf(dv * (A.z + fs.z) + bs[4 * fl + 2], 0.f);
            hr[3] = fmaxf(dv * (A.w + fs.w) + bs[4 * fl + 3], 0.f);
        }
    }
    __syncthreads();

    int nd = tid & 63, jh = tid >> 6;
    int j0 = jh * 8;
    unsigned long long acc2[4] = {0ull, 0ull, 0ull, 0ull};
    for (int k = 0; k < 64; k++) {
        float hv = Hs[nd * STR + k];
        unsigned long long h2 = f2pack(hv, hv);
        ulonglong2 wA = *(const ulonglong2*)&Ws[k * 32 + j0];
        ulonglong2 wB = *(const ulonglong2*)&Ws[k * 32 + j0 + 4];
        acc2[0] = f2fma(h2, wA.x, acc2[0]);
        acc2[1] = f2fma(h2, wA.y, acc2[1]);
        acc2[2] = f2fma(h2, wB.x, acc2[2]);
        acc2[3] = f2fma(h2, wB.y, acc2[3]);
    }
    int v = base + nd;
    if (v < n) {
        float s = 2.f * g_dinv[v];
        uint4 pk;
#pragma unroll
        for (int c = 0; c < 4; c++) {
            float2 f = f2unpack(acc2[c]);
            __half2 hh = __floats2half2_rn(s * f.x, s * f.y);
            ((uint32_t*)&pk)[c] = *(uint32_t*)&hh;
        }
        *(uint4*)(g_t2 + (size_t)v * 16 + jh * 4) = pk;
    }
}

// fused agg(32) + GEMM(32->16): 8-lane group per node (8 x uint2 = 64B row)
__global__ void __launch_bounds__(256)
k_f2(const float* __restrict__ bias, const float* __restrict__ Wg, int n) {
    constexpr int STR = 33;
    __shared__ float Hs[64 * STR];
    __shared__ float Ws[32 * 16];
    __shared__ float bs[32];
    int tid = threadIdx.x;
    for (int i = tid; i < 32 * 16; i += 256) Ws[i] = Wg[i];
    if (tid < 32) bs[tid] = bias[tid];
    int qw = tid >> 3, fl = tid & 7;
    int base = blockIdx.x * 64;
    const uint2* rb = (const uint2*)g_t2;

#pragma unroll
    for (int i = 0; i < 2; i++) {
        int nd = qw * 2 + i;
        int v = base + nd;
        if (v < n) {
            int s0 = g_rowstart[v], s1 = g_rowstart[v + 1];
            float4 A = gather_rows(rb, 8, fl, s0, s1);
            uint2 us = rb[(size_t)v * 8 + fl];
            float4 fs; cvt_u2(us, fs);
            float dv = g_dinv[v];
            float* hr = &Hs[nd * STR + 4 * fl];
            hr[0] = fmaxf(dv * (A.x + fs.x) + bs[4 * fl + 0], 0.f);
            hr[1] = fmaxf(dv * (A.y + fs.y) + bs[4 * fl + 1], 0.f);
            hr[2] = fmaxf(dv * (A.z + fs.z) + bs[4 * fl + 2], 0.f);
            hr[3] = fmaxf(dv * (A.w + fs.w) + bs[4 * fl + 3], 0.f);
        }
    }
    __syncthreads();

    int nd = tid & 63, jh = tid >> 6;
    int j0 = jh * 4;
    unsigned long long acc2[2] = {0ull, 0ull};
    for (int k = 0; k < 32; k++) {
        float hv = Hs[nd * STR + k];
        unsigned long long h2 = f2pack(hv, hv);
        ulonglong2 wv = *(const ulonglong2*)&Ws[k * 16 + j0];
        acc2[0] = f2fma(h2, wv.x, acc2[0]);
        acc2[1] = f2fma(h2, wv.y, acc2[1]);
    }
    int v = base + nd;
    if (v < n) {
        float s = 2.f * g_dinv[v];
        float2 f0 = f2unpack(acc2[0]), f1 = f2unpack(acc2[1]);
        uint2 pk;
        __half2 h0 = __floats2half2_rn(s * f0.x, s * f0.y);
        __half2 h1 = __floats2half2_rn(s * f1.x, s * f1.y);
        pk.x = *(uint32_t*)&h0; pk.y = *(uint32_t*)&h1;
        *(uint2*)(g_t3 + (size_t)v * 8 + jh * 2) = pk;
    }
}

// final agg (dim 16, 4-lane group per node) + block pooling + last-block MLP head
__global__ void __launch_bounds__(256)
k_aggpool(const float* __restrict__ bias, const void* batch, const void* ei,
          const float* __restrict__ fc1w, const float* __restrict__ fc1b,
          const float* __restrict__ fc2w, const float* __restrict__ fc2b,
          float* __restrict__ out, int n, int G) {
    __shared__ float spool[GMAX * 16];
    __shared__ float scnt[GMAX];
    __shared__ int sgmin, sgmax;
    __shared__ int s_flag;
    __shared__ bool s_last;
    int is64 = detect_is64(ei, &s_flag);
    int tid = threadIdx.x;
    for (int i = tid; i < GMAX * 16; i += 256) spool[i] = 0.f;
    if (tid < GMAX) scnt[tid] = 0.f;
    if (tid == 0) { sgmin = GMAX; sgmax = -1; }
    __syncthreads();
    int grp = tid >> 2, fl = tid & 3;
    int v = blockIdx.x * 64 + grp;
    const uint2* rb = (const uint2*)g_t3;
    if (v < n) {
        int s0 = g_rowstart[v], s1 = g_rowstart[v + 1];
        float4 A = gather_rows(rb, 4, fl, s0, s1);
        uint2 us = rb[(size_t)v * 4 + fl];
        float4 fs; cvt_u2(us, fs);
        float dv = g_dinv[v];
        int g = load_idx(batch, v, is64);
        int cb = 4 * fl;
        float h0 = fmaxf(dv * (A.x + fs.x) + bias[cb + 0], 0.f);
        float h1 = fmaxf(dv * (A.y + fs.y) + bias[cb + 1], 0.f);
        float h2 = fmaxf(dv * (A.z + fs.z) + bias[cb + 2], 0.f);
        float h3 = fmaxf(dv * (A.w + fs.w) + bias[cb + 3], 0.f);
        atomicAdd(&spool[g * 16 + cb + 0], h0);
        atomicAdd(&spool[g * 16 + cb + 1], h1);
        atomicAdd(&spool[g * 16 + cb + 2], h2);
        atomicAdd(&spool[g * 16 + cb + 3], h3);
        if (fl == 0) {
            atomicAdd(&scnt[g], 1.f);
            atomicMin(&sgmin, g);
            atomicMax(&sgmax, g);
        }
    }
    __syncthreads();
    int lo = sgmin, hi = sgmax;
    if (hi >= lo) {
        int rows = hi - lo + 1;
        for (int i = tid; i < rows * 16; i += 256) {
            float val = spool[(lo + i / 16) * 16 + (i & 15)];
            if (val != 0.f) atomicAdd(&g_m.pool[(lo + i / 16) * 16 + (i & 15)], val);
        }
        for (int i = tid; i < rows; i += 256) {
            float c = scnt[lo + i];
            if (c != 0.f) atomicAdd(&g_m.cnt[lo + i], c);
        }
    }
    if (tid == 0) {
        __threadfence();
        unsigned r = atomicAdd(&g_m.done, 1u);
        s_last = (r == gridDim.x - 1);
    }
    __syncthreads();
    if (s_last && tid < G) {
        int g = tid;
        float c = fmaxf(g_m.cnt[g], 1.f);
        float p[16];
#pragma unroll
        for (int j = 0; j < 16; j++) p[j] = g_m.pool[g * 16 + j] / c;
        float z[8];
#pragma unroll
        for (int i = 0; i < 8; i++) {
            float aa = fc1b[i];
#pragma unroll
            for (int j = 0; j < 16; j++) aa += p[j] * fc1w[j * 8 + i];
            z[i] = fmaxf(aa, 0.f);
        }
#pragma unroll
        for (int o = 0; o < 4; o++) {
            float aa = fc2b[o];
#pragma unroll
            for (int i = 0; i < 8; i++) aa += z[i] * fc2w[i * 4 + o];
            out[g * 4 + o] = aa;
        }
    }
}

// ------------------------------- host -------------------------------
extern "C" void kernel_launch(void* const* d_in, const int* in_sizes, int n_in,
                              void* d_out, int out_size) {
    const float* x   = (const float*)d_in[0];
    const void*  ei  = d_in[1];
    const void*  bat = d_in[2];
    const float* W0 = (const float*)d_in[3];  const float* b0 = (const float*)d_in[4];
    const float* W1 = (const float*)d_in[5];  const float* b1 = (const float*)d_in[6];
    const float* W2 = (const float*)d_in[7];  const float* b2 = (const float*)d_in[8];
    const float* W3 = (const float*)d_in[9];  const float* b3 = (const float*)d_in[10];
    const float* fc1w = (const float*)d_in[11]; const float* fc1b = (const float*)d_in[12];
    const float* fc2w = (const float*)d_in[13]; const float* fc2b = (const float*)d_in[14];
    float* out = (float*)d_out;

    int N = in_sizes[0] / 3;
    int E = in_sizes[1] / 2;
    int G = out_size / 4;
    if (N > NMAX || E > EMAX || G > GMAX) return;

    void* pHist = nullptr;
    cudaGetSymbolAddress(&pHist, g_hist);

    int gE = (E + 255) / 256;
    int nb = (N + 1023) / 1024;
    int smemL01 = 2048 + 18432 + 34816;   // 55296 B

    static int s_attr_done = 0;
    if (!s_attr_done) {
        cudaFuncSetAttribute(k_l01, cudaFuncAttributeMaxDynamicSharedMemorySize, smemL01);
        s_attr_done = 1;
    }

    cudaMemsetAsync(pHist, 0, (size_t)N * sizeof(int));
    k_hist<<<gE, 256>>>(ei, E);
    k_scan<<<nb, 256>>>(x, N);
    k_scatter<<<gE, 256>>>(E);
    k_agg0<<<(2 * N + 255) / 256, 256>>>(N);
    k_l01<<<(N + 383) / 384, 256, smemL01>>>(W0, b0, W1, N);
    k_f1<<<(N + 63) / 64, 256>>>(b1, W2, N);
    k_f2<<<(N + 63) / 64, 256>>>(b2, W3, N);
    k_aggpool<<<(N + 63) / 64, 256>>>(b3, bat, ei, fc1w, fc1b, fc2w, fc2b, out, N, G);
}

// round 17
// speedup vs baseline: 1.0430x; 1.0073x over previous
#include <cuda_runtime.h>
#include <cuda_fp16.h>
#include <cstdint>
#include <cstddef>

#define NMAX 100000
#define EMAX 1600000
#define GMAX 64
#define NB_MAX 128

// -------- device scratch --------
__device__ __half2 g_t1[(size_t)NMAX * 32];  // u1: N x 64 fp16 (dinv-scaled)
__device__ __half2 g_t2[(size_t)NMAX * 16];  // u2: N x 32 fp16
__device__ __half2 g_t3[(size_t)NMAX * 8];   // u3: N x 16 fp16
__device__ __half2 g_xh[(size_t)NMAX * 2];   // ux = dinv*x, padded half4
__device__ float   g_a[(size_t)NMAX * 4];    // aggregated x (N x 4) fp32
__device__ int2    g_epack[EMAX];            // packed {src,dst} int32
__device__ int     g_esrc[EMAX];             // src grouped by dst (CSR payload)
__device__ int     g_rowstart[NMAX + 1];
__device__ int     g_cursor[NMAX];
__device__ int     g_hist[NMAX];
__device__ float   g_dinv[NMAX];
__device__ float4  g_w0c[128];               // staged {W0 row, b0} float4
__device__ uint4   g_w1h[1152];              // staged W1 fp16, 128 x 72 layout (18432 B)

struct Misc {
    unsigned long long state[NB_MAX];
    float pool[GMAX * 16];
    float cnt[GMAX];
    unsigned int done;
};
__device__ Misc g_m;

__device__ __forceinline__ int load_idx(const void* p, int i, int is64) {
    if (is64) return (int)__ldg((const long long*)p + i);
    return __ldg((const int*)p + i);
}

__device__ __forceinline__ int detect_is64(const void* ei, int* s_flag) {
    if (threadIdx.x < 32) {
        const int* p = (const int*)ei;
        int v = p[2 * threadIdx.x + 1];
        unsigned any = __ballot_sync(0xffffffffu, v != 0);
        if (threadIdx.x == 0) *s_flag = (any == 0) ? 1 : 0;
    }
    __syncthreads();
    return *s_flag;
}

// packed f32x2 helpers
__device__ __forceinline__ unsigned long long f2fma(unsigned long long a, unsigned long long b,
                                                    unsigned long long c) {
    unsigned long long d;
    asm("fma.rn.f32x2 %0, %1, %2, %3;" : "=l"(d) : "l"(a), "l"(b), "l"(c));
    return d;
}
__device__ __forceinline__ unsigned long long f2pack(float x, float y) {
    unsigned long long r;
    asm("mov.b64 %0, {%1, %2};" : "=l"(r) : "f"(x), "f"(y));
    return r;
}
__device__ __forceinline__ float2 f2unpack(unsigned long long v) {
    float lo, hi;
    asm("mov.b64 {%0, %1}, %2;" : "=f"(lo), "=f"(hi) : "l"(v));
    return make_float2(lo, hi);
}

// mma helpers
__device__ __forceinline__ uint32_t smem_u32(const void* p) {
    uint32_t a;
    asm("{ .reg .u64 t; cvta.to.shared.u64 t, %1; cvt.u32.u64 %0, t; }" : "=r"(a) : "l"(p));
    return a;
}
__device__ __forceinline__ void ldsm_a(uint32_t addr, uint32_t r[4]) {
    asm volatile("ldmatrix.sync.aligned.m8n8.x4.shared.b16 {%0,%1,%2,%3}, [%4];"
                 : "=r"(r[0]), "=r"(r[1]), "=r"(r[2]), "=r"(r[3]) : "r"(addr));
}
__device__ __forceinline__ void ldsm_bt(uint32_t addr, uint32_t r[2]) {
    asm volatile("ldmatrix.sync.aligned.m8n8.x2.trans.shared.b16 {%0,%1}, [%2];"
                 : "=r"(r[0]), "=r"(r[1]) : "r"(addr));
}
__device__ __forceinline__ void mma16816(float d[4], const uint32_t a[4], const uint32_t b[2]) {
    asm volatile("mma.sync.aligned.m16n8k16.row.col.f32.f16.f16.f32 "
                 "{%0,%1,%2,%3}, {%4,%5,%6,%7}, {%8,%9}, {%0,%1,%2,%3};"
                 : "+f"(d[0]), "+f"(d[1]), "+f"(d[2]), "+f"(d[3])
                 : "r"(a[0]), "r"(a[1]), "r"(a[2]), "r"(a[3]), "r"(b[0]), "r"(b[1]));
}

__device__ __forceinline__ void cvt_u2(uint2 u, float4& f) {
    float2 lo = __half22float2(*(__half2*)&u.x);
    float2 hi = __half22float2(*(__half2*)&u.y);
    f = make_float4(lo.x, lo.y, hi.x, hi.y);
}

// group gather: SUM over edges of 8B row slices (uint2 per lane), 8/4/1 batching
__device__ __forceinline__ float4 gather_rows(const uint2* __restrict__ rb, int rstride,
                                              int fl, int s0, int s1) {
    float4 A = make_float4(0.f, 0.f, 0.f, 0.f);
    float4 B = make_float4(0.f, 0.f, 0.f, 0.f);
    int e = s0;
    for (; e + 7 < s1; e += 8) {
        int i0 = g_esrc[e],     i1 = g_esrc[e + 1], i2 = g_esrc[e + 2], i3 = g_esrc[e + 3];
        int i4 = g_esrc[e + 4], i5 = g_esrc[e + 5], i6 = g_esrc[e + 6], i7 = g_esrc[e + 7];
        uint2 u0 = rb[(size_t)i0 * rstride + fl], u1 = rb[(size_t)i1 * rstride + fl];
        uint2 u2 = rb[(size_t)i2 * rstride + fl], u3 = rb[(size_t)i3 * rstride + fl];
        uint2 u4 = rb[(size_t)i4 * rstride + fl], u5 = rb[(size_t)i5 * rstride + fl];
        uint2 u6 = rb[(size_t)i6 * rstride + fl], u7 = rb[(size_t)i7 * rstride + fl];
        float4 f0, f1, f2, f3, f4, f5, f6, f7;
        cvt_u2(u0, f0); cvt_u2(u1, f1); cvt_u2(u2, f2); cvt_u2(u3, f3);
        cvt_u2(u4, f4); cvt_u2(u5, f5); cvt_u2(u6, f6); cvt_u2(u7, f7);
        A.x += f0.x + f2.x + f4.x + f6.x; A.y += f0.y + f2.y + f4.y + f6.y;
        A.z += f0.z + f2.z + f4.z + f6.z; A.w += f0.w + f2.w + f4.w + f6.w;
        B.x += f1.x + f3.x + f5.x + f7.x; B.y += f1.y + f3.y + f5.y + f7.y;
        B.z += f1.z + f3.z + f5.z + f7.z; B.w += f1.w + f3.w + f5.w + f7.w;
    }
    if (e + 3 < s1) {
        int i0 = g_esrc[e], i1 = g_esrc[e + 1], i2 = g_esrc[e + 2], i3 = g_esrc[e + 3];
        uint2 u0 = rb[(size_t)i0 * rstride + fl], u1 = rb[(size_t)i1 * rstride + fl];
        uint2 u2 = rb[(size_t)i2 * rstride + fl], u3 = rb[(size_t)i3 * rstride + fl];
        float4 f0, f1, f2, f3;
        cvt_u2(u0, f0); cvt_u2(u1, f1); cvt_u2(u2, f2); cvt_u2(u3, f3);
        A.x += f0.x + f2.x; A.y += f0.y + f2.y; A.z += f0.z + f2.z; A.w += f0.w + f2.w;
        B.x += f1.x + f3.x; B.y += f1.y + f3.y; B.z += f1.z + f3.z; B.w += f1.w + f3.w;
        e += 4;
    }
    for (; e < s1; e++) {
        uint2 u = rb[(size_t)g_esrc[e] * rstride + fl];
        float4 f; cvt_u2(u, f);
        A.x += f.x; A.y += f.y; A.z += f.z; A.w += f.w;
    }
    A.x += B.x; A.y += B.y; A.z += B.z; A.w += B.w;
    return A;
}

// histogram + pack int64->int2 (+ block 0: zero g_m, stage W0/b0/W1-fp16)
__global__ void k_hist(const void* ei, const float* __restrict__ W0,
                       const float* __restrict__ b0, const float* __restrict__ W1, int E) {
    __shared__ int s_flag;
    int is64 = detect_is64(ei, &s_flag);
    if (blockIdx.x == 0) {
        int tid = threadIdx.x;
        for (int i = tid; i < (int)(sizeof(Misc) / 4); i += blockDim.x)
            ((unsigned*)&g_m)[i] = 0u;
        if (tid < 128)
            g_w0c[tid] = make_float4(W0[tid], W0[128 + tid], W0[256 + tid], b0[tid]);
        __half* w1h = (__half*)g_w1h;
        for (int i = tid; i < 128 * 64; i += blockDim.x) {
            int k = i >> 6, nn = i & 63;
            w1h[k * 72 + nn] = __float2half_rn(W1[i]);
        }
    }
    int e = blockIdx.x * blockDim.x + threadIdx.x;
    if (e >= E) return;
    int s = load_idx(ei, e, is64);
    int d = load_idx(ei, E + e, is64);
    g_epack[e] = make_int2(s, d);
    atomicAdd(&g_hist[d], 1);
}

// single-pass decoupled-lookback scan + dinv + x->fp16 conversion + cursor init
__global__ void __launch_bounds__(256) k_scan(const float* __restrict__ x, int n) {
    __shared__ int sh[256];
    __shared__ int s_pref;
    int t = threadIdx.x, b = blockIdx.x;
    int base = b * 1024 + t * 4;
    int h[4]; int s = 0;
#pragma unroll
    for (int q = 0; q < 4; q++) { int i = base + q; h[q] = (i < n) ? g_hist[i] : 0; s += h[q]; }
    sh[t] = s;
    __syncthreads();
    for (int off = 1; off < 256; off <<= 1) {
        int u = (t >= off) ? sh[t - off] : 0;
        __syncthreads();
        sh[t] += u;
        __syncthreads();
    }
    int total = sh[255];
    if (t == 0) {
        unsigned long long val = ((b == 0) ? (2ULL << 32) : (1ULL << 32)) | (unsigned)total;
        atomicExch(&g_m.state[b], val);
        int pfx = 0;
        for (int j = b - 1; j >= 0;) {
            unsigned long long v;
            do { v = atomicAdd(&g_m.state[j], 0ULL); } while (v == 0ULL);
            pfx += (int)(v & 0xffffffffu);
            if ((v >> 32) == 2ULL) break;
            j--;
        }
        s_pref = pfx;
        if (b > 0) atomicExch(&g_m.state[b], (2ULL << 32) | (unsigned)(pfx + total));
    }
    __syncthreads();
    int pref = s_pref;
    int off0 = pref + sh[t] - s;
#pragma unroll
    for (int q = 0; q < 4; q++) {
        int i = base + q;
        if (i < n) {
            g_rowstart[i] = off0;
            g_cursor[i]   = off0;
            float dv = rsqrtf((float)(h[q] + 1));
            g_dinv[i] = dv;
            float x0 = x[3 * (size_t)i], x1 = x[3 * (size_t)i + 1], x2 = x[3 * (size_t)i + 2];
            g_xh[2 * (size_t)i]     = __floats2half2_rn(dv * x0, dv * x1);
            g_xh[2 * (size_t)i + 1] = __floats2half2_rn(dv * x2, 0.f);
            off0 += h[q];
        }
    }
    if (b == gridDim.x - 1 && t == 255) g_rowstart[n] = pref + total;
}

__global__ void k_scatter(int E) {
    int e = blockIdx.x * blockDim.x + threadIdx.x;
    if (e >= E) return;
    int2 sd = g_epack[e];
    int pos = atomicAdd(&g_cursor[sd.y], 1);
    g_esrc[pos] = sd.x;
}

// aggregate ux at dim 3 -> g_a (2 threads per node, alternate edges, shfl combine)
__global__ void k_agg0(int n) {
    int gid = blockIdx.x * blockDim.x + threadIdx.x;
    int v = gid >> 1, h = gid & 1;
    if (v >= n) return;
    int s0 = g_rowstart[v], s1 = g_rowstart[v + 1];
    const uint2* xp = (const uint2*)g_xh;
    float a0 = 0.f, a1 = 0.f, a2 = 0.f, b0 = 0.f, b1 = 0.f, b2 = 0.f;
    int e = s0 + h;
    for (; e + 6 < s1; e += 8) {
        uint2 ra = xp[g_esrc[e]],     rb = xp[g_esrc[e + 2]];
        uint2 rc = xp[g_esrc[e + 4]], rd = xp[g_esrc[e + 6]];
        float2 fa = __half22float2(*(__half2*)&ra.x); float fa2 = __low2float(*(__half2*)&ra.y);
        float2 fb = __half22float2(*(__half2*)&rb.x); float fb2 = __low2float(*(__half2*)&rb.y);
        float2 fc = __half22float2(*(__half2*)&rc.x); float fc2 = __low2float(*(__half2*)&rc.y);
        float2 fd = __half22float2(*(__half2*)&rd.x); float fd2 = __low2float(*(__half2*)&rd.y);
        a0 += fa.x + fc.x; a1 += fa.y + fc.y; a2 += fa2 + fc2;
        b0 += fb.x + fd.x; b1 += fb.y + fd.y; b2 += fb2 + fd2;
    }
    for (; e < s1; e += 2) {
        uint2 ra = xp[g_esrc[e]];
        float2 fa = __half22float2(*(__half2*)&ra.x); float fa2 = __low2float(*(__half2*)&ra.y);
        a0 += fa.x; a1 += fa.y; a2 += fa2;
    }
    float r0 = a0 + b0, r1 = a1 + b1, r2 = a2 + b2;
    r0 += __shfl_xor_sync(0xffffffffu, r0, 1);
    r1 += __shfl_xor_sync(0xffffffffu, r1, 1);
    r2 += __shfl_xor_sync(0xffffffffu, r2, 1);
    if (h == 0) {
        uint2 rs = xp[v];
        float2 fs = __half22float2(*(__half2*)&rs.x); float fs2 = __low2float(*(__half2*)&rs.y);
        float dv = g_dinv[v];
        *(float4*)(g_a + 4 * (size_t)v) =
            make_float4(dv * (r0 + fs.x), dv * (r1 + fs.y), dv * (r2 + fs2), 0.f);
    }
}

// layers 0+1 on tensor cores, 3 node-tiles (384 nodes) per block; weights pre-staged
#define HS_STR 136
#define W1_STR 72
__global__ void __launch_bounds__(256)
k_l01(int n) {
    extern __shared__ char sm_[];
    float4* W0c = (float4*)sm_;                       // 2048 B
    __half* W1h = (__half*)(sm_ + 2048);              // 18432 B
    __half* Hs  = (__half*)(sm_ + 2048 + 18432);      // 34816 B
    int tid = threadIdx.x;
    if (tid < 128) W0c[tid] = g_w0c[tid];
    {
        uint4* dst = (uint4*)W1h;
#pragma unroll
        for (int r = 0; r < 5; r++) {
            int i = tid + r * 256;
            if (i < 1152) dst[i] = g_w1h[i];
        }
    }
    __syncthreads();

    int w = tid >> 5, lane = tid & 31;
    int m0 = (w & 7) * 16;
    int gid = lane >> 2, qid = lane & 3;
    int a_row = m0 + ((lane >> 3) & 1) * 8 + (lane & 7);
    int a_col0 = ((lane >> 4) & 1) * 8;
    int b_lane = lane & 15;
    uint32_t hsb = smem_u32(Hs);
    uint32_t w1b = smem_u32(W1h);

#pragma unroll
    for (int tile = 0; tile < 3; tile++) {
        int base = (blockIdx.x * 3 + tile) * 128;
        if (base >= n) break;

        // Phase A: h = relu(a·W0 + b0) -> Hs fp16 (2 threads per node)
        {
            int node = tid >> 1, jh = tid & 1;
            int v = base + node;
            float4 a = (v < n) ? *(const float4*)(g_a + 4 * (size_t)v) : make_float4(0, 0, 0, 0);
            __half2* hrow = (__half2*)(Hs + node * HS_STR + jh * 64);
#pragma unroll
            for (int k2 = 0; k2 < 32; k2++) {
                float4 w0 = W0c[jh * 64 + 2 * k2];
                float4 w1 = W0c[jh * 64 + 2 * k2 + 1];
                float h0 = fmaxf(fmaf(a.x, w0.x, fmaf(a.y, w0.y, fmaf(a.z, w0.z, w0.w))), 0.f);
                float h1 = fmaxf(fmaf(a.x, w1.x, fmaf(a.y, w1.y, fmaf(a.z, w1.z, w1.w))), 0.f);
                hrow[k2] = __floats2half2_rn(h0, h1);
            }
        }
        __syncthreads();

        // Phase B: 128x128 @ 128x64 HMMA
        float acc[8][4];
#pragma unroll
        for (int nt = 0; nt < 8; nt++)
#pragma unroll
            for (int c = 0; c < 4; c++) acc[nt][c] = 0.f;

#pragma unroll
        for (int ks = 0; ks < 8; ks++) {
            uint32_t af[4];
            ldsm_a(hsb + (uint32_t)(a_row * HS_STR + ks * 16 + a_col0) * 2, af);
            int b_row = ks * 16 + b_lane;
#pragma unroll
            for (int nt = 0; nt < 8; nt++) {
                uint32_t bf[2];
                ldsm_bt(w1b + (uint32_t)(b_row * W1_STR + nt * 8) * 2, bf);
                mma16816(acc[nt], af, bf);
            }
        }

        int r0 = base + m0 + gid, r1 = r0 + 8;
        float s0 = (r0 < n) ? 2.f * g_dinv[r0] : 0.f;
        float s1 = (r1 < n) ? 2.f * g_dinv[r1] : 0.f;
        __half* t1h = (__half*)g_t1;
#pragma unroll
        for (int nt = 0; nt < 8; nt++) {
            int col = nt * 8 + qid * 2;
            if (r0 < n)
                *(__half2*)(t1h + (size_t)r0 * 64 + col) = __floats2half2_rn(s0 * acc[nt][0], s0 * acc[nt][1]);
            if (r1 < n)
                *(__half2*)(t1h + (size_t)r1 * 64 + col) = __floats2half2_rn(s1 * acc[nt][2], s1 * acc[nt][3]);
        }
        __syncthreads();   // Hs reuse across tiles
    }
}

// fused agg(64) + GEMM(64->32): half-warp per node (16 lanes x uint2 = 128B row)
__global__ void __launch_bounds__(256)
k_f1(const float* __restrict__ bias, const float* __restrict__ Wg, int n) {
    constexpr int STR = 65;
    __shared__ float Hs[64 * STR];
    __shared__ float Ws[64 * 32];
    __shared__ float bs[64];
    int tid = threadIdx.x;
    for (int i = tid; i < 64 * 32; i += 256) Ws[i] = Wg[i];
    if (tid < 64) bs[tid] = bias[tid];
    int hw = tid >> 4, fl = tid & 15;
    int base = blockIdx.x * 64;
    const uint2* rb = (const uint2*)g_t1;

#pragma unroll
    for (int i = 0; i < 4; i++) {
        int nd = hw * 4 + i;
        int v = base + nd;
        if (v < n) {
            int s0 = g_rowstart[v], s1 = g_rowstart[v + 1];
            float4 A = gather_rows(rb, 16, fl, s0, s1);
            uint2 us = rb[(size_t)v * 16 + fl];
            float4 fs; cvt_u2(us, fs);
            float dv = g_dinv[v];
            float* hr = &Hs[nd * STR + 4 * fl];
            hr[0] = fmaxf(dv * (A.x + fs.x) + bs[4 * fl + 0], 0.f);
            hr[1] = fmaxf(dv * (A.y + fs.y) + bs[4 * fl + 1], 0.f);
            hr[2] = fmaxf(dv * (A.z + fs.z) + bs[4 * fl + 2], 0.f);
            hr[3] = fmaxf(dv * (A.w + fs.w) + bs[4 * fl + 3], 0.f);
        }
    }
    __syncthreads();

    int nd = tid & 63, jh = tid >> 6;
    int j0 = jh * 8;
    unsigned long long acc2[4] = {0ull, 0ull, 0ull, 0ull};
    for (int k = 0; k < 64; k++) {
        float hv = Hs[nd * STR + k];
        unsigned long long h2 = f2pack(hv, hv);
        ulonglong2 wA = *(const ulonglong2*)&Ws[k * 32 + j0];
        ulonglong2 wB = *(const ulonglong2*)&Ws[k * 32 + j0 + 4];
        acc2[0] = f2fma(h2, wA.x, acc2[0]);
        acc2[1] = f2fma(h2, wA.y, acc2[1]);
        acc2[2] = f2fma(h2, wB.x, acc2[2]);
        acc2[3] = f2fma(h2, wB.y, acc2[3]);
    }
    int v = base + nd;
    if (v < n) {
        float s = 2.f * g_dinv[v];
        uint4 pk;
#pragma unroll
        for (int c = 0; c < 4; c++) {
            float2 f = f2unpack(acc2[c]);
            __half2 hh = __floats2half2_rn(s * f.x, s * f.y);
            ((uint32_t*)&pk)[c] = *(uint32_t*)&hh;
        }
        *(uint4*)(g_t2 + (size_t)v * 16 + jh * 4) = pk;
    }
}

// fused agg(32) + GEMM(32->16): 8-lane group per node (8 x uint2 = 64B row)
__global__ void __launch_bounds__(256)
k_f2(const float* __restrict__ bias, const float* __restrict__ Wg, int n) {
    constexpr int STR = 33;
    __shared__ float Hs[64 * STR];
    __shared__ float Ws[32 * 16];
    __shared__ float bs[32];
    int tid = threadIdx.x;
    for (int i = tid; i < 32 * 16; i += 256) Ws[i] = Wg[i];
    if (tid < 32) bs[tid] = bias[tid];
    int qw = tid >> 3, fl = tid & 7;
    int base = blockIdx.x * 64;
    const uint2* rb = (const uint2*)g_t2;

#pragma unroll
    for (int i = 0; i < 2; i++) {
        int nd = qw * 2 + i;
        int v = base + nd;
        if (v < n) {
            int s0 = g_rowstart[v], s1 = g_rowstart[v + 1];
            float4 A = gather_rows(rb, 8, fl, s0, s1);
            uint2 us = rb[(size_t)v * 8 + fl];
            float4 fs; cvt_u2(us, fs);
            float dv = g_dinv[v];
            float* hr = &Hs[nd * STR + 4 * fl];
            hr[0] = fmaxf(dv * (A.x + fs.x) + bs[4 * fl + 0], 0.f);
            hr[1] = fmaxf(dv * (A.y + fs.y) + bs[4 * fl + 1], 0.f);
            hr[2] = fmaxf(dv * (A.z + fs.z) + bs[4 * fl + 2], 0.f);
            hr[3] = fmaxf(dv * (A.w + fs.w) + bs[4 * fl + 3], 0.f);
        }
    }
    __syncthreads();

    int nd = tid & 63, jh = tid >> 6;
    int j0 = jh * 4;
    unsigned long long acc2[2] = {0ull, 0ull};
    for (int k = 0; k < 32; k++) {
        float hv = Hs[nd * STR + k];
        unsigned long long h2 = f2pack(hv, hv);
        ulonglong2 wv = *(const ulonglong2*)&Ws[k * 16 + j0];
        acc2[0] = f2fma(h2, wv.x, acc2[0]);
        acc2[1] = f2fma(h2, wv.y, acc2[1]);
    }
    int v = base + nd;
    if (v < n) {
        float s = 2.f * g_dinv[v];
        float2 f0 = f2unpack(acc2[0]), f1 = f2unpack(acc2[1]);
        uint2 pk;
        __half2 h0 = __floats2half2_rn(s * f0.x, s * f0.y);
        __half2 h1 = __floats2half2_rn(s * f1.x, s * f1.y);
        pk.x = *(uint32_t*)&h0; pk.y = *(uint32_t*)&h1;
        *(uint2*)(g_t3 + (size_t)v * 8 + jh * 2) = pk;
    }
}

// final agg (dim 16, 4-lane group per node) + block pooling + last-block MLP head
__global__ void __launch_bounds__(256)
k_aggpool(const float* __restrict__ bias, const void* batch, const void* ei,
          const float* __restrict__ fc1w, const float* __restrict__ fc1b,
          const float* __restrict__ fc2w, const float* __restrict__ fc2b,
          float* __restrict__ out, int n, int G) {
    __shared__ float spool[GMAX * 16];
    __shared__ float scnt[GMAX];
    __shared__ int sgmin, sgmax;
    __shared__ int s_flag;
    __shared__ bool s_last;
    int is64 = detect_is64(ei, &s_flag);
    int tid = threadIdx.x;
    for (int i = tid; i < GMAX * 16; i += 256) spool[i] = 0.f;
    if (tid < GMAX) scnt[tid] = 0.f;
    if (tid == 0) { sgmin = GMAX; sgmax = -1; }
    __syncthreads();
    int grp = tid >> 2, fl = tid & 3;
    int v = blockIdx.x * 64 + grp;
    const uint2* rb = (const uint2*)g_t3;
    if (v < n) {
        int s0 = g_rowstart[v], s1 = g_rowstart[v + 1];
        float4 A = gather_rows(rb, 4, fl, s0, s1);
        uint2 us = rb[(size_t)v * 4 + fl];
        float4 fs; cvt_u2(us, fs);
        float dv = g_dinv[v];
        int g = load_idx(batch, v, is64);
        int cb = 4 * fl;
        float h0 = fmaxf(dv * (A.x + fs.x) + bias[cb + 0], 0.f);
        float h1 = fmaxf(dv * (A.y + fs.y) + bias[cb + 1], 0.f);
        float h2 = fmaxf(dv * (A.z + fs.z) + bias[cb + 2], 0.f);
        float h3 = fmaxf(dv * (A.w + fs.w) + bias[cb + 3], 0.f);
        atomicAdd(&spool[g * 16 + cb + 0], h0);
        atomicAdd(&spool[g * 16 + cb + 1], h1);
        atomicAdd(&spool[g * 16 + cb + 2], h2);
        atomicAdd(&spool[g * 16 + cb + 3], h3);
        if (fl == 0) {
            atomicAdd(&scnt[g], 1.f);
            atomicMin(&sgmin, g);
            atomicMax(&sgmax, g);
        }
    }
    __syncthreads();
    int lo = sgmin, hi = sgmax;
    if (hi >= lo) {
        int rows = hi - lo + 1;
        for (int i = tid; i < rows * 16; i += 256) {
            float val = spool[(lo + i / 16) * 16 + (i & 15)];
            if (val != 0.f) atomicAdd(&g_m.pool[(lo + i / 16) * 16 + (i & 15)], val);
        }
        for (int i = tid; i < rows; i += 256) {
            float c = scnt[lo + i];
            if (c != 0.f) atomicAdd(&g_m.cnt[lo + i], c);
        }
    }
    if (tid == 0) {
        __threadfence();
        unsigned r = atomicAdd(&g_m.done, 1u);
        s_last = (r == gridDim.x - 1);
    }
    __syncthreads();
    if (s_last && tid < G) {
        int g = tid;
        float c = fmaxf(g_m.cnt[g], 1.f);
        float p[16];
#pragma unroll
        for (int j = 0; j < 16; j++) p[j] = g_m.pool[g * 16 + j] / c;
        float z[8];
#pragma unroll
        for (int i = 0; i < 8; i++) {
            float aa = fc1b[i];
#pragma unroll
            for (int j = 0; j < 16; j++) aa += p[j] * fc1w[j * 8 + i];
            z[i] = fmaxf(aa, 0.f);
        }
#pragma unroll
        for (int o = 0; o < 4; o++) {
            float aa = fc2b[o];
#pragma unroll
            for (int i = 0; i < 8; i++) aa += z[i] * fc2w[i * 4 + o];
            out[g * 4 + o] = aa;
        }
    }
}

// ------------------------------- host -------------------------------
extern "C" void kernel_launch(void* const* d_in, const int* in_sizes, int n_in,
                              void* d_out, int out_size) {
    const float* x   = (const float*)d_in[0];
    const void*  ei  = d_in[1];
    const void*  bat = d_in[2];
    const float* W0 = (const float*)d_in[3];  const float* b0 = (const float*)d_in[4];
    const float* W1 = (const float*)d_in[5];  const float* b1 = (const float*)d_in[6];
    const float* W2 = (const float*)d_in[7];  const float* b2 = (const float*)d_in[8];
    const float* W3 = (const float*)d_in[9];  const float* b3 = (const float*)d_in[10];
    const float* fc1w = (const float*)d_in[11]; const float* fc1b = (const float*)d_in[12];
    const float* fc2w = (const float*)d_in[13]; const float* fc2b = (const float*)d_in[14];
    float* out = (float*)d_out;

    int N = in_sizes[0] / 3;
    int E = in_sizes[1] / 2;
    int G = out_size / 4;
    if (N > NMAX || E > EMAX || G > GMAX) return;

    void* pHist = nullptr;
    cudaGetSymbolAddress(&pHist, g_hist);

    int gE = (E + 255) / 256;
    int nb = (N + 1023) / 1024;
    int smemL01 = 2048 + 18432 + 34816;   // 55296 B

    static int s_attr_done = 0;
    if (!s_attr_done) {
        cudaFuncSetAttribute(k_l01, cudaFuncAttributeMaxDynamicSharedMemorySize, smemL01);
        s_attr_done = 1;
    }

    cudaMemsetAsync(pHist, 0, (size_t)N * sizeof(int));
    k_hist<<<gE, 256>>>(ei, W0, b0, W1, E);
    k_scan<<<nb, 256>>>(x, N);
    k_scatter<<<gE, 256>>>(E);
    k_agg0<<<(2 * N + 255) / 256, 256>>>(N);
    k_l01<<<(N + 383) / 384, 256, smemL01>>>(N);
    k_f1<<<(N + 63) / 64, 256>>>(b1, W2, N);
    k_f2<<<(N + 63) / 64, 256>>>(b2, W3, N);
    k_aggpool<<<(N + 63) / 64, 256>>>(b3, bat, ei, fc1w, fc1b, fc2w, fc2b, out, N, G);
}